// round 1
// baseline (speedup 1.0000x reference)
#include <cuda_runtime.h>
#include <math.h>

#define B_  2
#define S_  2048
#define D_  1024
#define H_  16
#define DEPTH_ 64
#define MROWS (B_*S_)          // 4096
#define OUT_ELEMS  ((size_t)B_*S_*D_)            // 4194304
#define ATTN_ELEMS ((size_t)B_*H_*S_*S_)         // 134217728

// ---- static device scratch (allocation-free rule) ----
__device__ float g_qh[B_*H_*S_*DEPTH_];   // 16 MB each
__device__ float g_kh[B_*H_*S_*DEPTH_];
__device__ float g_vh[B_*H_*S_*DEPTH_];
__device__ float g_pre[B_*S_*D_];
__device__ float g_attn_fallback[1];      // only used if out buffer lacks attn space (shouldn't happen)

// ============================================================
// Projection GEMM: out = X(4096x1024) @ W(1024x1024) + bias
// headed=1: write to (B,H,S,depth) layout; headed=0: flat (row,col)
// BM=BN=64, BK=16, 16x16 threads, 4x4 per thread
// ============================================================
__global__ void proj_kernel(const float* __restrict__ X, const float* __restrict__ W,
                            const float* __restrict__ bias, float* __restrict__ out,
                            int headed)
{
    __shared__ float As[16][65];   // [kk][row_local]
    __shared__ float Bs[16][64];   // [kk][col_local]
    const int tx = threadIdx.x, ty = threadIdx.y;
    const int tid = ty*16 + tx;
    const int row0 = blockIdx.y * 64;
    const int col0 = blockIdx.x * 64;

    float acc[4][4] = {};

    for (int k0 = 0; k0 < 1024; k0 += 16) {
        #pragma unroll
        for (int t = 0; t < 4; ++t) {
            int idx = tid + 256*t;            // 0..1023
            int r  = idx >> 4;
            int kk = idx & 15;
            As[kk][r] = X[(size_t)(row0 + r)*1024 + k0 + kk];
        }
        #pragma unroll
        for (int t = 0; t < 4; ++t) {
            int idx = tid + 256*t;
            int kk = idx >> 6;
            int c  = idx & 63;
            Bs[kk][c] = W[(size_t)(k0 + kk)*1024 + col0 + c];
        }
        __syncthreads();
        #pragma unroll
        for (int kk = 0; kk < 16; ++kk) {
            float a[4], b[4];
            #pragma unroll
            for (int i = 0; i < 4; ++i) a[i] = As[kk][ty + 16*i];
            #pragma unroll
            for (int j = 0; j < 4; ++j) b[j] = Bs[kk][tx + 16*j];
            #pragma unroll
            for (int i = 0; i < 4; ++i)
                #pragma unroll
                for (int j = 0; j < 4; ++j)
                    acc[i][j] += a[i]*b[j];
        }
        __syncthreads();
    }

    #pragma unroll
    for (int i = 0; i < 4; ++i) {
        int row = row0 + ty + 16*i;
        #pragma unroll
        for (int j = 0; j < 4; ++j) {
            int col = col0 + tx + 16*j;
            float v = acc[i][j] + bias[col];
            if (headed) {
                int b = row >> 11;           // /2048
                int s = row & 2047;
                int h = col >> 6;            // /64
                int d = col & 63;
                out[(((size_t)(b*H_ + h))*S_ + s)*DEPTH_ + d] = v;
            } else {
                out[(size_t)row*D_ + col] = v;
            }
        }
    }
}

// ============================================================
// Logits: attn[bh,q,k] = scale * dot(qh[bh,q], kh[bh,k]) + m*(-1e17)
// m = max(mask[b,k], causal(k>q))
// Skips dot product for fully-masked blocks (k0 > q0+63).
// ============================================================
__global__ void logits_kernel(const float* __restrict__ mask, float* __restrict__ attn)
{
    const int bh = blockIdx.z;
    const int b  = bh / H_;
    const int q0 = blockIdx.y * 64;
    const int k0 = blockIdx.x * 64;
    const int tx = threadIdx.x, ty = threadIdx.y;
    const int tid = ty*16 + tx;
    const float scale = 0.125f;   // 1/sqrt(64)

    float* arow = attn + ((size_t)bh*S_)*S_;

    if (k0 >= q0 + 64) {
        // fully masked block: value is m * (-1e17) (logits term vanishes in fp32 rounding)
        #pragma unroll
        for (int i = 0; i < 4; ++i) {
            int qr = q0 + ty + 16*i;
            #pragma unroll
            for (int j = 0; j < 4; ++j) {
                int kc = k0 + tx + 16*j;
                float m = fmaxf(mask[(size_t)b*S_ + kc], 1.0f);
                arow[(size_t)qr*S_ + kc] = m * (-1e17f);
            }
        }
        return;
    }

    __shared__ float Qs[64][65];   // [d][row]
    __shared__ float Ks[64][65];   // [d][row]
    const float* Q = g_qh + (size_t)bh*S_*DEPTH_;
    const float* K = g_kh + (size_t)bh*S_*DEPTH_;

    #pragma unroll
    for (int t = 0; t < 16; ++t) {
        int idx = tid + 256*t;     // 0..4095
        int r = idx >> 6;
        int d = idx & 63;
        Qs[d][r] = Q[(size_t)(q0 + r)*DEPTH_ + d];
        Ks[d][r] = K[(size_t)(k0 + r)*DEPTH_ + d];
    }
    __syncthreads();

    float acc[4][4] = {};
    #pragma unroll
    for (int d = 0; d < 64; ++d) {
        float a[4], b_[4];
        #pragma unroll
        for (int i = 0; i < 4; ++i) a[i]  = Qs[d][ty + 16*i];
        #pragma unroll
        for (int j = 0; j < 4; ++j) b_[j] = Ks[d][tx + 16*j];
        #pragma unroll
        for (int i = 0; i < 4; ++i)
            #pragma unroll
            for (int j = 0; j < 4; ++j)
                acc[i][j] += a[i]*b_[j];
    }

    #pragma unroll
    for (int i = 0; i < 4; ++i) {
        int qr = q0 + ty + 16*i;
        #pragma unroll
        for (int j = 0; j < 4; ++j) {
            int kc = k0 + tx + 16*j;
            float causal = (kc > qr) ? 1.0f : 0.0f;
            float m = fmaxf(mask[(size_t)b*S_ + kc], causal);
            arow[(size_t)qr*S_ + kc] = acc[i][j]*scale + m * (-1e17f);
        }
    }
}

// ============================================================
// Row softmax in place over attn rows of length S_ (one block per row)
// ============================================================
__global__ void softmax_kernel(float* __restrict__ attn)
{
    const size_t row = blockIdx.x;
    float* p = attn + row * S_;
    const int tid = threadIdx.x;   // 256 threads

    __shared__ float red[32];

    // max
    float lmax = -INFINITY;
    for (int i = tid; i < S_; i += 256) lmax = fmaxf(lmax, p[i]);
    #pragma unroll
    for (int o = 16; o > 0; o >>= 1) lmax = fmaxf(lmax, __shfl_xor_sync(0xffffffffu, lmax, o));
    if ((tid & 31) == 0) red[tid >> 5] = lmax;
    __syncthreads();
    if (tid < 32) {
        float v = (tid < 8) ? red[tid] : -INFINITY;
        #pragma unroll
        for (int o = 4; o > 0; o >>= 1) v = fmaxf(v, __shfl_xor_sync(0xffffffffu, v, o));
        if (tid == 0) red[0] = v;
    }
    __syncthreads();
    float rowmax = red[0];
    __syncthreads();

    // exp + sum
    float lsum = 0.0f;
    for (int i = tid; i < S_; i += 256) {
        float e = __expf(p[i] - rowmax);
        p[i] = e;
        lsum += e;
    }
    #pragma unroll
    for (int o = 16; o > 0; o >>= 1) lsum += __shfl_xor_sync(0xffffffffu, lsum, o);
    if ((tid & 31) == 0) red[tid >> 5] = lsum;
    __syncthreads();
    if (tid < 32) {
        float v = (tid < 8) ? red[tid] : 0.0f;
        #pragma unroll
        for (int o = 4; o > 0; o >>= 1) v += __shfl_xor_sync(0xffffffffu, v, o);
        if (tid == 0) red[0] = v;
    }
    __syncthreads();
    float inv = 1.0f / red[0];

    for (int i = tid; i < S_; i += 256) p[i] *= inv;
}

// ============================================================
// out_h = attn @ V per (b,h); causal-truncated k loop.
// Writes into g_pre in (B, S, D) layout.
// ============================================================
__global__ void av_kernel(const float* __restrict__ attn)
{
    const int bh = blockIdx.y;
    const int q0 = blockIdx.x * 64;
    const int b = bh / H_, h = bh % H_;
    const int tx = threadIdx.x, ty = threadIdx.y;
    const int tid = ty*16 + tx;

    __shared__ float As[64][65];   // attn tile [r][c]
    __shared__ float Vs[64][65];   // V tile   [k][d]

    const float* A = attn + ((size_t)bh*S_)*S_;
    const float* V = g_vh + (size_t)bh*S_*DEPTH_;

    float acc[4][4] = {};

    for (int k0 = 0; k0 <= q0; k0 += 64) {     // cols > q0+63 are exact zeros
        #pragma unroll
        for (int t = 0; t < 16; ++t) {
            int idx = tid + 256*t;
            int r = idx >> 6;
            int c = idx & 63;
            As[r][c] = A[(size_t)(q0 + r)*S_ + k0 + c];
            Vs[r][c] = V[(size_t)(k0 + r)*DEPTH_ + c];
        }
        __syncthreads();
        #pragma unroll
        for (int c = 0; c < 64; ++c) {
            float a[4], b_[4];
            #pragma unroll
            for (int i = 0; i < 4; ++i) a[i]  = As[ty + 16*i][c];
            #pragma unroll
            for (int j = 0; j < 4; ++j) b_[j] = Vs[c][tx + 16*j];
            #pragma unroll
            for (int i = 0; i < 4; ++i)
                #pragma unroll
                for (int j = 0; j < 4; ++j)
                    acc[i][j] += a[i]*b_[j];
        }
        __syncthreads();
    }

    #pragma unroll
    for (int i = 0; i < 4; ++i) {
        int s = q0 + ty + 16*i;
        #pragma unroll
        for (int j = 0; j < 4; ++j) {
            int d = tx + 16*j;
            g_pre[((size_t)b*S_ + s)*D_ + h*DEPTH_ + d] = acc[i][j];
        }
    }
}

// ============================================================
extern "C" void kernel_launch(void* const* d_in, const int* in_sizes, int n_in,
                              void* d_out, int out_size)
{
    (void)in_sizes; (void)n_in;
    const float* v    = (const float*)d_in[0];
    const float* k    = (const float*)d_in[1];
    const float* q    = (const float*)d_in[2];
    const float* mask = (const float*)d_in[3];
    const float* Wq   = (const float*)d_in[4];
    const float* bq   = (const float*)d_in[5];
    const float* Wk   = (const float*)d_in[6];
    const float* bk   = (const float*)d_in[7];
    const float* Wv   = (const float*)d_in[8];
    const float* bv   = (const float*)d_in[9];
    const float* Wo   = (const float*)d_in[10];
    const float* bo   = (const float*)d_in[11];

    float* out = (float*)d_out;

    float *qh, *kh, *vh;
    cudaGetSymbolAddress((void**)&qh, g_qh);
    cudaGetSymbolAddress((void**)&kh, g_kh);
    cudaGetSymbolAddress((void**)&vh, g_vh);

    // attn lives in d_out (tuple order: out first, then attn)
    float* attn;
    if ((size_t)out_size >= OUT_ELEMS + ATTN_ELEMS) {
        attn = out + OUT_ELEMS;
    } else {
        cudaGetSymbolAddress((void**)&attn, g_attn_fallback);  // degenerate; not expected
    }

    dim3 tb(16, 16);

    // Q/K/V projections into headed layout
    dim3 gproj(D_/64, MROWS/64);   // (16, 64)
    proj_kernel<<<gproj, tb>>>(q, Wq, bq, qh, 1);
    proj_kernel<<<gproj, tb>>>(k, Wk, bk, kh, 1);
    proj_kernel<<<gproj, tb>>>(v, Wv, bv, vh, 1);

    // logits with mask
    dim3 glog(S_/64, S_/64, B_*H_);   // (32,32,32)
    logits_kernel<<<glog, tb>>>(mask, attn);

    // softmax per row
    softmax_kernel<<<B_*H_*S_, 256>>>(attn);

    // attn @ V -> g_pre (B,S,D)
    dim3 gav(S_/64, B_*H_);
    av_kernel<<<gav, tb>>>(attn);

    // final projection: out = pre @ Wo + bo
    float* pre;
    cudaGetSymbolAddress((void**)&pre, g_pre);
    proj_kernel<<<gproj, tb>>>(pre, Wo, bo, out, 0);
}